// round 16
// baseline (speedup 1.0000x reference)
#include <cuda_runtime.h>
#include <math.h>

#define NB 32
#define NP 1024
#define NL 32
#define NH 128
#define SW 136   // smem row stride (words) for paired-k TC kernels

__device__ float g_text [NB*NL*NH];
__device__ float g_mask [NB*NP];
__device__ float g_cnt  [NB];
__device__ float g_tgtc [NB*NL*NP];
__device__ float g_nl   [NB*NL];
__device__ float g_lsec [NB*NP];
__device__ float g_iou  [NB*NL];
__device__ float g_lpm  [NB*8*NL];
__device__ float g_lps  [NB*8*NL];
__device__ float g_lpt  [NB*8*NL];
__device__ float g_lsp  [NB*8*NL];
__device__ float4   g_vp  [NB*8*NL*32];
__device__ int      g_pos [NB*NP];
__device__ int      g_cntI[NB];
__device__ unsigned g_boxc [NB*NP*NH];
__device__ unsigned g_boxlc[NB*NP*NH];
__device__ unsigned g_wpt[NH*NH];   // Wp as tf32 bits
__device__ unsigned g_wit[NH*NH];   // Wpi as tf32 bits

__device__ __forceinline__ unsigned f2tf(float f) {
    unsigned u; asm("cvt.rna.tf32.f32 %0, %1;" : "=r"(u) : "f"(f)); return u;
}
__device__ __forceinline__ uint4 f2tf4(float4 v) {
    return make_uint4(f2tf(v.x), f2tf(v.y), f2tf(v.z), f2tf(v.w));
}
__device__ __forceinline__ void mma_tf32(float* c, const unsigned* a, const unsigned* bb) {
    asm volatile("mma.sync.aligned.m16n8k8.row.col.f32.tf32.tf32.f32 "
                 "{%0,%1,%2,%3}, {%4,%5,%6,%7}, {%8,%9}, {%0,%1,%2,%3};"
                 : "+f"(c[0]), "+f"(c[1]), "+f"(c[2]), "+f"(c[3])
                 : "r"(a[0]), "r"(a[1]), "r"(a[2]), "r"(a[3]), "r"(bb[0]), "r"(bb[1]));
}
__device__ __forceinline__ int lang_num_at(const int* ln, int b) {
    return (ln[1] == 0) ? ln[2*b] : ln[b];
}

// ---------------- W -> tf32 pre-convert ----------------
__global__ void k_wconv(const float* __restrict__ Wp, const float* __restrict__ Wpi) {
    int i = blockIdx.x*512 + threadIdx.x;   // 4096 uint4s
    *(uint4*)&g_wpt[i*4] = f2tf4(((const float4*)Wp)[i]);
    *(uint4*)&g_wit[i*4] = f2tf4(((const float4*)Wpi)[i]);
}

// ---------------- mask + prefix-scan compaction ----------------
__global__ __launch_bounds__(1024) void k_maskscan(const float* __restrict__ obj) {
    int b = blockIdx.x, tid = threadIdx.x, lane = tid&31, w = tid>>5;
    __shared__ int wc[32], wo[32];
    float s0 = obj[(b*NP+tid)*2], s1 = obj[(b*NP+tid)*2+1];
    int m = (s1 > s0);
    g_mask[b*NP+tid] = m ? 1.f : 0.f;
    unsigned bal = __ballot_sync(~0u, m);
    int before = __popc(bal & ((1u<<lane)-1u));
    if (lane==0) wc[w] = __popc(bal);
    __syncthreads();
    if (tid < 32) {
        int v = wc[tid];
        #pragma unroll
        for (int o=1;o<32;o<<=1){ int t=__shfl_up_sync(~0u,v,o); if (lane>=o) v+=t; }
        wo[tid] = v - wc[tid];
        if (tid==31) { g_cntI[b] = v; g_cnt[b] = (float)v; }
    }
    __syncthreads();
    g_pos[b*NP+tid] = wo[w] + before;
    int cnt = g_cntI[b];
    int padded = (cnt + 127) & ~127;
    for (int e = cnt*NH + tid; e < padded*NH; e += 1024) {
        g_boxc [b*NP*NH + e] = 0u;
        g_boxlc[b*NP*NH + e] = 0u;
    }
}

// ---------------- targets: one block per batch ----------------
__global__ __launch_bounds__(1024) void k_tgt(const float* __restrict__ pc, const float* __restrict__ ps,
                      const float* __restrict__ gc, const float* __restrict__ gs) {
    int b = blockIdx.x, tid = threadIdx.x, lane = tid & 31;
    __shared__ float sg[NL*6];
    __shared__ int sh_nl[NL];
    if (tid < NL*3) {
        int l = tid/3, d = tid - l*3;
        sg[l*6+d]   = gc[(b*NL+l)*3+d];
        sg[l*6+3+d] = gs[(b*NL+l)*3+d] + 0.01f;
    }
    if (tid < NL) sh_nl[tid] = 0;
    float cc[3], ss[3];
    int base = (b*NP+tid)*3;
    #pragma unroll
    for (int d = 0; d < 3; d++) { cc[d] = pc[base+d]; ss[d] = ps[base+d]; }
    float volp = ss[0]*ss[1]*ss[2];
    float mk = g_mask[b*NP+tid];
    int pos = g_pos[b*NP+tid];
    int cnt = g_cntI[b];
    __syncthreads();
    for (int l = 0; l < NL; l++) {
        float volg = sg[l*6+3]*sg[l*6+4]*sg[l*6+5];
        float inter = 1.f;
        #pragma unroll
        for (int d = 0; d < 3; d++) {
            float lo = fmaxf(sg[l*6+d]-0.5f*sg[l*6+3+d], cc[d]-ss[d]*0.5f);
            float hi = fminf(sg[l*6+d]+0.5f*sg[l*6+3+d], cc[d]+ss[d]*0.5f);
            inter *= fmaxf(hi-lo, 0.f);
        }
        float iou = inter / (volg + volp - inter + 1e-7f);
        bool pos_t = (iou > 0.25f) && (mk > 0.f);
        float* trow = g_tgtc + (b*NL+l)*NP;
        if (mk > 0.f) trow[pos] = pos_t ? 1.f : 0.f;
        if (tid >= cnt) trow[tid] = 0.f;
        unsigned bal = __ballot_sync(~0u, pos_t);
        if (lane == 0 && bal) atomicAdd(&sh_nl[l], __popc(bal));
    }
    __syncthreads();
    if (tid < NL) g_nl[b*NL+tid] = (float)sh_nl[tid];
}

// ---------------- k_text: tf32 TC, paired-k LDS.64 ----------------
#define TEXT_SMEM (2*128*SW*4)
__global__ __launch_bounds__(256) void k_text_tc(const float* __restrict__ emb,
                                                 const float* __restrict__ Wt) {
    extern __shared__ unsigned su[];
    unsigned* av = su;
    unsigned* wt = su + 128*SW;
    const int r0 = blockIdx.x*128, tid = threadIdx.x;
    const float4* e4 = (const float4*)(emb + r0*NH);
    const float4* w4 = (const float4*)Wt;
    for (int idx = tid; idx < 4096; idx += 256) {
        int r = idx >> 5, k4 = idx & 31;
        *(uint4*)&av[r*SW + k4*4] = f2tf4(e4[idx]);
        *(uint4*)&wt[r*SW + k4*4] = f2tf4(w4[idx]);
    }
    __syncthreads();
    const int wid = tid>>5, lane = tid&31, g = lane>>2, t4 = lane&3;
    float acc[16][4];
    #pragma unroll
    for (int nf=0;nf<16;nf++)
        #pragma unroll
        for (int i=0;i<4;i++) acc[nf][i]=0.f;
    #pragma unroll
    for (int ks = 0; ks < 16; ks++) {
        const int k0 = ks*8 + 2*t4;
        uint2 aP0 = *(uint2*)&av[(wid*16 + g)*SW + k0];
        uint2 aP1 = *(uint2*)&av[(wid*16 + g + 8)*SW + k0];
        unsigned af[4] = { aP0.x, aP1.x, aP0.y, aP1.y };
        #pragma unroll
        for (int nf = 0; nf < 16; nf++) {
            uint2 bP = *(uint2*)&wt[(nf*8 + g)*SW + k0];
            unsigned bf[2] = { bP.x, bP.y };
            mma_tf32(acc[nf], af, bf);
        }
    }
    float sA = 0.f, sB = 0.f;
    #pragma unroll
    for (int nf = 0; nf < 16; nf++) {
        sA += acc[nf][0]*acc[nf][0] + acc[nf][1]*acc[nf][1];
        sB += acc[nf][2]*acc[nf][2] + acc[nf][3]*acc[nf][3];
    }
    #pragma unroll
    for (int o = 1; o < 4; o <<= 1) {
        sA += __shfl_xor_sync(~0u, sA, o);
        sB += __shfl_xor_sync(~0u, sB, o);
    }
    float iA = 1.f/fmaxf(sqrtf(sA), 1e-12f);
    float iB = 1.f/fmaxf(sqrtf(sB), 1e-12f);
    int rA = r0 + wid*16 + g, rB = rA + 8;
    #pragma unroll
    for (int nf = 0; nf < 16; nf++) {
        *(float2*)&g_text[rA*NH + nf*8 + t4*2] = make_float2(acc[nf][0]*iA, acc[nf][1]*iA);
        *(float2*)&g_text[rB*NH + nf*8 + t4*2] = make_float2(acc[nf][2]*iB, acc[nf][3]*iB);
    }
}

// ---------------- k_proj: 64-row blocks, W from global, 2 CTAs/SM ----------------
#define PROJ_SMEM_C (64*SW*4 + 256*4)
__global__ __launch_bounds__(512, 2) void k_proj(const float* __restrict__ bbox) {
    extern __shared__ unsigned su[];
    unsigned* av = su;                 // [64][SW]
    float* pn = (float*)(su + 64*SW);  // [2 colhalf][2 matrix][64]
    const int m0 = blockIdx.x*64, b = m0 >> 10;
    const int tid = threadIdx.x;
    const float4* a4 = (const float4*)(bbox + (long)m0*NH);
    for (int idx = tid; idx < 2048; idx += 512) {
        int r = idx >> 5, k4 = idx & 31;
        *(uint4*)&av[r*SW + k4*4] = f2tf4(a4[idx]);
    }
    __syncthreads();
    const int wid = tid>>5, lane = tid&31, g = lane>>2, t4 = lane&3;
    const int wm = wid & 3, wn = wid >> 2;
    const int mat = wn >> 1, ch = wn & 1;
    const unsigned* W = mat ? g_wit : g_wpt;
    float acc[8][4];
    #pragma unroll
    for (int nf=0;nf<8;nf++)
        #pragma unroll
        for (int i=0;i<4;i++) acc[nf][i] = 0.f;
    #pragma unroll
    for (int ks = 0; ks < 16; ks++) {
        const int k0 = ks*8 + 2*t4;
        uint2 aP0 = *(uint2*)&av[(wm*16 + g)*SW + k0];
        uint2 aP1 = *(uint2*)&av[(wm*16 + g + 8)*SW + k0];
        unsigned af[4] = { aP0.x, aP1.x, aP0.y, aP1.y };
        #pragma unroll
        for (int nf = 0; nf < 8; nf++) {
            uint2 bP = __ldg((const uint2*)&W[(ch*64 + nf*8 + g)*NH + k0]);
            unsigned bf[2] = { bP.x, bP.y };
            mma_tf32(acc[nf], af, bf);
        }
    }
    float sA = 0.f, sB = 0.f;
    #pragma unroll
    for (int nf = 0; nf < 8; nf++) {
        sA += acc[nf][0]*acc[nf][0] + acc[nf][1]*acc[nf][1];
        sB += acc[nf][2]*acc[nf][2] + acc[nf][3]*acc[nf][3];
    }
    #pragma unroll
    for (int o = 1; o < 4; o <<= 1) {
        sA += __shfl_xor_sync(~0u, sA, o);
        sB += __shfl_xor_sync(~0u, sB, o);
    }
    const int rA = wm*16 + g, rB = rA + 8;
    if (t4 == 0) {
        pn[ch*128 + mat*64 + rA] = sA;
        pn[ch*128 + mat*64 + rB] = sB;
    }
    __syncthreads();
    float nA = pn[mat*64 + rA] + pn[128 + mat*64 + rA];
    float nB = pn[mat*64 + rB] + pn[128 + mat*64 + rB];
    float iA = 1.f/fmaxf(sqrtf(nA), 1e-12f);
    float iB = 1.f/fmaxf(sqrtf(nB), 1e-12f);
    unsigned* cbase = mat ? g_boxc : g_boxlc;
    #pragma unroll
    for (int rr = 0; rr < 2; rr++) {
        int gp = m0 + (rr ? rB : rA);
        float inv = rr ? iB : iA;
        if (g_mask[gp] > 0.f) {
            unsigned* cdst = cbase + ((long)b*NP + g_pos[gp])*NH + ch*64 + t4*2;
            #pragma unroll
            for (int nf = 0; nf < 8; nf++)
                *(uint2*)(cdst + nf*8) =
                    make_uint2(f2tf(acc[nf][rr*2]*inv), f2tf(acc[nf][rr*2+1]*inv));
        }
    }
}

// ---------------- k_iou: B in smem, A via L1 LDG, 2 CTAs/SM ----------------
#define IOU_TC_SMEM (128*SW*4 + (128 + 2*2*128 + 2*128)*4)
__global__ __launch_bounds__(512, 2) void k_iou_tc() {
    extern __shared__ unsigned smu[];
    unsigned* bs = smu;
    float* ms  = (float*)(smu + 128*SW);
    float* pm  = ms + 128;
    float* ps  = pm + 256;
    float* rmS = ps + 256;
    float* rsS = rmS + 128;

    const int b = blockIdx.y, r0 = blockIdx.x*128, tid = threadIdx.x;
    const int cnt = g_cntI[b];
    if (r0 >= cnt) return;
    const int qtiles = (cnt + 127) >> 7;
    const int wid = tid >> 5, lane = tid & 31;
    const int g = lane >> 2, t4 = lane & 3;
    const int wm = wid & 7, wn = wid >> 3;
    const unsigned* Arow = g_boxc + ((long)b*NP + r0)*NH;

    if (tid < 128) { rmS[tid] = -1e30f; rsS[tid] = 0.f; }

    for (int qt = 0; qt < qtiles; qt++) {
        __syncthreads();
        const uint4* Xb = (const uint4*)(g_boxc + ((long)b*NP + qt*128)*NH);
        for (int idx = tid; idx < 4096; idx += 512) {
            int q = idx >> 5, k4 = idx & 31;
            *(uint4*)&bs[q*SW + k4*4] = Xb[idx];
        }
        if (tid < 128) ms[tid] = (qt*128 + tid < cnt) ? 1.f : 0.f;
        __syncthreads();

        float acc[8][4];
        #pragma unroll
        for (int nf=0;nf<8;nf++)
            #pragma unroll
            for (int i=0;i<4;i++) acc[nf][i] = 0.f;
        #pragma unroll
        for (int ks = 0; ks < 16; ks++) {
            const int k0 = ks*8 + 2*t4;
            uint2 aP0 = __ldg((const uint2*)&Arow[(wm*16 + g)*NH + k0]);
            uint2 aP1 = __ldg((const uint2*)&Arow[(wm*16 + g + 8)*NH + k0]);
            unsigned af[4] = { aP0.x, aP1.x, aP0.y, aP1.y };
            #pragma unroll
            for (int nf = 0; nf < 8; nf++) {
                uint2 bP = *(uint2*)&bs[(wn*64 + nf*8 + g)*SW + k0];
                unsigned bf[2] = { bP.x, bP.y };
                mma_tf32(acc[nf], af, bf);
            }
        }
        float cm0[8], cm1[8];
        #pragma unroll
        for (int nf = 0; nf < 8; nf++) {
            cm0[nf] = ms[wn*64 + nf*8 + t4*2];
            cm1[nf] = ms[wn*64 + nf*8 + t4*2 + 1];
        }
        {
            const int rA = wm*16 + g, rB = rA + 8;
            float mA = -1e30f, mB = -1e30f;
            #pragma unroll
            for (int nf = 0; nf < 8; nf++) {
                mA = fmaxf(mA, (cm0[nf] > 0.f) ? acc[nf][0] : -1e30f);
                mA = fmaxf(mA, (cm1[nf] > 0.f) ? acc[nf][1] : -1e30f);
                mB = fmaxf(mB, (cm0[nf] > 0.f) ? acc[nf][2] : -1e30f);
                mB = fmaxf(mB, (cm1[nf] > 0.f) ? acc[nf][3] : -1e30f);
            }
            #pragma unroll
            for (int o = 1; o < 4; o <<= 1) {
                mA = fmaxf(mA, __shfl_xor_sync(~0u, mA, o));
                mB = fmaxf(mB, __shfl_xor_sync(~0u, mB, o));
            }
            float eA = 0.f, eB = 0.f;
            #pragma unroll
            for (int nf = 0; nf < 8; nf++) {
                eA += (cm0[nf] > 0.f) ? __expf(acc[nf][0] - mA) : 0.f;
                eA += (cm1[nf] > 0.f) ? __expf(acc[nf][1] - mA) : 0.f;
                eB += (cm0[nf] > 0.f) ? __expf(acc[nf][2] - mB) : 0.f;
                eB += (cm1[nf] > 0.f) ? __expf(acc[nf][3] - mB) : 0.f;
            }
            #pragma unroll
            for (int o = 1; o < 4; o <<= 1) {
                eA += __shfl_xor_sync(~0u, eA, o);
                eB += __shfl_xor_sync(~0u, eB, o);
            }
            if (t4 == 0) {
                pm[wn*128 + rA] = mA; ps[wn*128 + rA] = eA;
                pm[wn*128 + rB] = mB; ps[wn*128 + rB] = eB;
            }
        }
        __syncthreads();
        if (tid < 128) {
            float m0 = pm[tid], s0 = ps[tid], m1 = pm[128+tid], s1 = ps[128+tid];
            float tm = fmaxf(m0, m1);
            float te = ((s0 > 0.f) ? s0*__expf(m0 - tm) : 0.f)
                     + ((s1 > 0.f) ? s1*__expf(m1 - tm) : 0.f);
            float rm = rmS[tid], nm = fmaxf(rm, tm);
            float rs = rsS[tid];
            rs = ((rs > 0.f) ? rs*__expf(rm - nm) : 0.f)
               + ((te > 0.f) ? te*__expf(tm - nm) : 0.f);
            rmS[tid] = nm; rsS[tid] = rs;
        }
    }
    __syncthreads();
    if (tid < 128) {
        int r = r0 + tid;
        if (r < cnt)
            g_lsec[b*NP + r] = (rsS[tid] > 0.f) ? rmS[tid] + logf(rsS[tid]) : 0.f;
    }
}

// ---------------- k_lang_part: paired-k LDS.64 ----------------
#define LANGP_SMEM ((32*SW + 128*SW)*4 + (128 + 3*256)*4)
__global__ __launch_bounds__(512, 2) void k_lang_part() {
    const int qt = blockIdx.x, b = blockIdx.y, tid = threadIdx.x;
    const int cnt = g_cntI[b];
    if (qt*128 >= cnt) {
        if (tid < 32) {
            int o = (b*8+qt)*NL + tid;
            g_lpm[o] = -1e30f; g_lps[o] = 0.f; g_lpt[o] = 0.f;
        }
        return;
    }
    extern __shared__ unsigned smu[];
    unsigned* at = smu;
    unsigned* bs = smu + 32*SW;
    float* ms = (float*)(smu + 32*SW + 128*SW);
    float* pm = ms + 128;
    float* ps = pm + 256;
    float* pt = ps + 256;
    const int wid = tid >> 5, lane = tid & 31;
    const int g = lane >> 2, t4 = lane & 3;
    const int wm = wid & 1, wn = wid >> 1;

    const float4* tx4 = (const float4*)(g_text + b*NL*NH);
    for (int idx = tid; idx < 1024; idx += 512) {
        int r = idx >> 5, k4 = idx & 31;
        *(uint4*)&at[r*SW + k4*4] = f2tf4(tx4[idx]);
    }
    const uint4* Xb = (const uint4*)(g_boxlc + ((long)b*NP + qt*128)*NH);
    for (int idx = tid; idx < 4096; idx += 512) {
        int q = idx >> 5, k4 = idx & 31;
        *(uint4*)&bs[q*SW + k4*4] = Xb[idx];
    }
    if (tid < 128) ms[tid] = (qt*128 + tid < cnt) ? 1.f : 0.f;
    __syncthreads();

    float acc[2][4];
    #pragma unroll
    for (int nf=0;nf<2;nf++)
        #pragma unroll
        for (int i=0;i<4;i++) acc[nf][i] = 0.f;
    #pragma unroll
    for (int ks = 0; ks < 16; ks++) {
        const int k0 = ks*8 + 2*t4;
        uint2 aP0 = *(uint2*)&at[(wm*16 + g)*SW + k0];
        uint2 aP1 = *(uint2*)&at[(wm*16 + g + 8)*SW + k0];
        unsigned af[4] = { aP0.x, aP1.x, aP0.y, aP1.y };
        #pragma unroll
        for (int nf = 0; nf < 2; nf++) {
            uint2 bP = *(uint2*)&bs[(wn*16 + nf*8 + g)*SW + k0];
            unsigned bf[2] = { bP.x, bP.y };
            mma_tf32(acc[nf], af, bf);
        }
    }
    const int rA = wm*16 + g, rB = rA + 8;
    float mA = -1e30f, mB = -1e30f, tA = 0.f, tB = 0.f;
    float m0v[2], m1v[2];
    #pragma unroll
    for (int nf = 0; nf < 2; nf++) {
        int col0 = wn*16 + nf*8 + t4*2;
        m0v[nf] = ms[col0]; m1v[nf] = ms[col0 + 1];
        float2 tgA = *(float2*)&g_tgtc[(b*NL + rA)*NP + qt*128 + col0];
        float2 tgB = *(float2*)&g_tgtc[(b*NL + rB)*NP + qt*128 + col0];
        tA += tgA.x*acc[nf][0] + tgA.y*acc[nf][1];
        tB += tgB.x*acc[nf][2] + tgB.y*acc[nf][3];
        mA = fmaxf(mA, (m0v[nf] > 0.f) ? acc[nf][0] : -1e30f);
        mA = fmaxf(mA, (m1v[nf] > 0.f) ? acc[nf][1] : -1e30f);
        mB = fmaxf(mB, (m0v[nf] > 0.f) ? acc[nf][2] : -1e30f);
        mB = fmaxf(mB, (m1v[nf] > 0.f) ? acc[nf][3] : -1e30f);
    }
    #pragma unroll
    for (int o = 1; o < 4; o <<= 1) {
        mA = fmaxf(mA, __shfl_xor_sync(~0u, mA, o));
        mB = fmaxf(mB, __shfl_xor_sync(~0u, mB, o));
    }
    float eA = 0.f, eB = 0.f;
    #pragma unroll
    for (int nf = 0; nf < 2; nf++) {
        eA += (m0v[nf] > 0.f) ? __expf(acc[nf][0] - mA) : 0.f;
        eA += (m1v[nf] > 0.f) ? __expf(acc[nf][1] - mA) : 0.f;
        eB += (m0v[nf] > 0.f) ? __expf(acc[nf][2] - mB) : 0.f;
        eB += (m1v[nf] > 0.f) ? __expf(acc[nf][3] - mB) : 0.f;
    }
    #pragma unroll
    for (int o = 1; o < 4; o <<= 1) {
        eA += __shfl_xor_sync(~0u, eA, o);
        eB += __shfl_xor_sync(~0u, eB, o);
        tA += __shfl_xor_sync(~0u, tA, o);
        tB += __shfl_xor_sync(~0u, tB, o);
    }
    if (t4 == 0) {
        pm[wn*32 + rA] = mA; ps[wn*32 + rA] = eA; pt[wn*32 + rA] = tA;
        pm[wn*32 + rB] = mB; ps[wn*32 + rB] = eB; pt[wn*32 + rB] = tB;
    }
    __syncthreads();
    if (tid < 32) {
        float m = -1e30f, s = 0.f, t = 0.f;
        #pragma unroll
        for (int wg = 0; wg < 8; wg++) {
            float om = pm[wg*32 + tid], os = ps[wg*32 + tid];
            float nm = fmaxf(m, om);
            s = ((s > 0.f) ? s*__expf(m - nm) : 0.f)
              + ((os > 0.f) ? os*__expf(om - nm) : 0.f);
            m = nm;
            t += pt[wg*32 + tid];
        }
        int o = (b*8+qt)*NL + tid;
        g_lpm[o] = m; g_lps[o] = s; g_lpt[o] = t;
    }
}

// ---------------- k_vsum_part ----------------
#define VSP_SMEM ((32*132 + 128*132)*4)
__global__ __launch_bounds__(512, 2) void k_vsum_part() {
    const int qt = blockIdx.x, b = blockIdx.y, tid = threadIdx.x;
    const int cnt = g_cntI[b];
    float4* vp = g_vp + (b*8+qt)*NL*32;
    if (qt*128 >= cnt) {
        for (int i = tid; i < NL*32; i += 512) vp[i] = make_float4(0.f,0.f,0.f,0.f);
        if (tid < 32) g_lsp[(b*8+qt)*NL + tid] = 0.f;
        return;
    }
    extern __shared__ unsigned smu[];
    unsigned* at = smu;
    unsigned* bs = smu + 32*132;
    const int wid = tid >> 5, lane = tid & 31;
    const int g = lane >> 2, t4 = lane & 3;
    const int wm = wid & 1, wn = wid >> 1;

    const uint4* tg4 = (const uint4*)(g_tgtc + b*NL*NP + qt*128);  // 0/1.0f bits are valid tf32
    for (int idx = tid; idx < 1024; idx += 512) {
        int r = idx >> 5, k4 = idx & 31;
        *(uint4*)&at[r*132 + k4*4] = tg4[r*256 + k4];
    }
    const uint4* Xb = (const uint4*)(g_boxc + ((long)b*NP + qt*128)*NH);
    for (int idx = tid; idx < 4096; idx += 512) {
        int q = idx >> 5, k4 = idx & 31;
        *(uint4*)&bs[q*132 + k4*4] = Xb[idx];
    }
    __syncthreads();

    float acc[2][4];
    #pragma unroll
    for (int nf=0;nf<2;nf++)
        #pragma unroll
        for (int i=0;i<4;i++) acc[nf][i] = 0.f;
    #pragma unroll
    for (int ks = 0; ks < 16; ks++) {
        const int k0 = ks*8;
        unsigned af[4];
        int base = (wm*16 + g)*132 + k0 + t4;
        af[0] = at[base];
        af[1] = at[base + 8*132];
        af[2] = at[base + 4];
        af[3] = at[base + 8*132 + 4];
        #pragma unroll
        for (int nf = 0; nf < 2; nf++) {
            int ncol = wn*16 + nf*8 + g;
            unsigned bf[2] = { bs[(k0+t4)*132 + ncol], bs[(k0+t4+4)*132 + ncol] };
            mma_tf32(acc[nf], af, bf);
        }
    }
    float* vpf = (float*)vp;
    const int rA = wm*16 + g, rB = rA + 8;
    #pragma unroll
    for (int nf = 0; nf < 2; nf++) {
        int col0 = wn*16 + nf*8 + t4*2;
        *(float2*)(vpf + rA*NH + col0) = make_float2(acc[nf][0], acc[nf][1]);
        *(float2*)(vpf + rB*NH + col0) = make_float2(acc[nf][2], acc[nf][3]);
    }
    int jmax = min(128, cnt - qt*128);
    #pragma unroll
    for (int li = 0; li < 2; li++) {
        int l = wid*2 + li;
        float s = 0.f;
        for (int j = lane; j < jmax; j += 32)
            s += g_tgtc[(b*NL+l)*NP + qt*128 + j] * g_lsec[b*NP + qt*128 + j];
        #pragma unroll
        for (int o = 16; o; o >>= 1) s += __shfl_xor_sync(~0u, s, o);
        if (lane == 0) g_lsp[(b*8+qt)*NL + l] = s;
    }
}

// ---------------- k_vfold ----------------
__global__ __launch_bounds__(1024) void k_vfold(const int* __restrict__ ln) {
    int b = blockIdx.x, tid = threadIdx.x;
    int l = tid >> 5, lane = tid & 31;
    float4 v = make_float4(0.f,0.f,0.f,0.f);
    #pragma unroll
    for (int qt = 0; qt < 8; qt++) {
        float4 p = g_vp[((b*8+qt)*NL + l)*32 + lane];
        v.x += p.x; v.y += p.y; v.z += p.z; v.w += p.w;
    }
    float vv = v.x*v.x + v.y*v.y + v.z*v.z + v.w*v.w;
    float s = (lane < 8) ? g_lsp[(b*8+lane)*NL + l] : 0.f;
    #pragma unroll
    for (int o = 16; o; o >>= 1) {
        vv += __shfl_xor_sync(~0u, vv, o);
        s  += __shfl_xor_sync(~0u, s, o);
    }
    if (lane == 0) {
        float n = g_nl[b*NL+l];
        float cnt1 = fmaxf(g_cnt[b], 1.f);
        float val = (n > 0.f) ? (n*s - vv)/(cnt1*cnt1) : 0.f;
        g_iou[b*NL+l] = (l < lang_num_at(ln, b)) ? val : 0.f;
    }
}

// ---------------- k_final ----------------
__global__ void k_final(const int* __restrict__ ln, float* __restrict__ out) {
    int tid = threadIdx.x;
    int b = tid >> 5, l = tid & 31;
    float m = -1e30f, s = 0.f, t = 0.f;
    #pragma unroll
    for (int qt = 0; qt < 8; qt++) {
        int o = (b*8+qt)*NL + l;
        float om = g_lpm[o], os = g_lps[o];
        float nm = fmaxf(m, om);
        s = ((s > 0.f) ? s*__expf(m - nm) : 0.f)
          + ((os > 0.f) ? os*__expf(om - nm) : 0.f);
        m = nm;
        t += g_lpt[o];
    }
    float n = g_nl[tid];
    float cnt1 = fmaxf(g_cnt[b], 1.f);
    float a = 0.f;
    if (n > 0.f && s > 0.f) a = 0.5f*(n*(m + logf(s)) - t)/cnt1;
    if (l >= lang_num_at(ln, b)) a = 0.f;
    float c = g_iou[tid];
    for (int o = 16; o; o >>= 1) {
        a += __shfl_xor_sync(~0u, a, o);
        c += __shfl_xor_sync(~0u, c, o);
    }
    __shared__ float ra[32], rc[32];
    if ((tid&31)==0) { ra[tid>>5]=a; rc[tid>>5]=c; }
    __syncthreads();
    if (tid < 32) {
        a = ra[tid]; c = rc[tid];
        for (int o = 16; o; o >>= 1) {
            a += __shfl_xor_sync(~0u, a, o);
            c += __shfl_xor_sync(~0u, c, o);
        }
        if (tid == 0) { out[0] = a/(float)NB; out[1] = c/(float)NB; }
    }
}

extern "C" void kernel_launch(void* const* d_in, const int* in_sizes, int n_in,
                              void* d_out, int out_size) {
    const float* pred_center = (const float*)d_in[0];
    const float* pred_size   = (const float*)d_in[1];
    const float* bbox        = (const float*)d_in[2];
    const float* gt_center   = (const float*)d_in[3];
    const float* gt_size     = (const float*)d_in[4];
    const float* lang_emb    = (const float*)d_in[5];
    const float* obj         = (const float*)d_in[6];
    const float* Wt          = (const float*)d_in[7];
    const float* Wp          = (const float*)d_in[8];
    const float* Wpi         = (const float*)d_in[9];
    const int*   lang_num    = (const int*)d_in[10];
    float* out = (float*)d_out;

    static bool attr_done = false;
    if (!attr_done) {
        cudaFuncSetAttribute(k_proj, cudaFuncAttributeMaxDynamicSharedMemorySize, PROJ_SMEM_C);
        cudaFuncSetAttribute(k_iou_tc, cudaFuncAttributeMaxDynamicSharedMemorySize, IOU_TC_SMEM);
        cudaFuncSetAttribute(k_text_tc, cudaFuncAttributeMaxDynamicSharedMemorySize, TEXT_SMEM);
        cudaFuncSetAttribute(k_lang_part, cudaFuncAttributeMaxDynamicSharedMemorySize, LANGP_SMEM);
        cudaFuncSetAttribute(k_vsum_part, cudaFuncAttributeMaxDynamicSharedMemorySize, VSP_SMEM);
        attr_done = true;
    }

    k_wconv<<<8, 512>>>(Wp, Wpi);
    k_maskscan<<<NB, 1024>>>(obj);
    k_tgt<<<NB, 1024>>>(pred_center, pred_size, gt_center, gt_size);
    k_text_tc<<<(NB*NL)/128, 256, TEXT_SMEM>>>(lang_emb, Wt);
    k_proj<<<(NB*NP)/64, 512, PROJ_SMEM_C>>>(bbox);
    k_iou_tc<<<dim3(NP/128, NB), 512, IOU_TC_SMEM>>>();
    k_lang_part<<<dim3(8, NB), 512, LANGP_SMEM>>>();
    k_vsum_part<<<dim3(8, NB), 512, VSP_SMEM>>>();
    k_vfold<<<NB, 1024>>>(lang_num);
    k_final<<<1, 1024>>>(lang_num, out);
}

// round 17
// speedup vs baseline: 1.6775x; 1.6775x over previous
#include <cuda_runtime.h>
#include <math.h>

#define NB 32
#define NP 1024
#define NL 32
#define NH 128
#define SW 136   // smem row stride (words) for paired-k TC kernels

__device__ float g_text [NB*NL*NH];
__device__ float g_mask [NB*NP];
__device__ float g_cnt  [NB];
__device__ float g_tgtc [NB*NL*NP];
__device__ float g_nl   [NB*NL];
__device__ float g_lsec [NB*NP];
__device__ float g_iou  [NB*NL];
__device__ float g_lpm  [NB*8*NL];
__device__ float g_lps  [NB*8*NL];
__device__ float g_lpt  [NB*8*NL];
__device__ float g_lsp  [NB*8*NL];
__device__ float4   g_vp  [NB*8*NL*32];
__device__ int      g_pos [NB*NP];
__device__ int      g_cntI[NB];
__device__ unsigned g_boxc [NB*NP*NH];
__device__ unsigned g_boxlc[NB*NP*NH];

// ---------------- mask + prefix-scan compaction ----------------
__global__ __launch_bounds__(1024) void k_maskscan(const float* __restrict__ obj) {
    int b = blockIdx.x, tid = threadIdx.x, lane = tid&31, w = tid>>5;
    __shared__ int wc[32], wo[32];
    float s0 = obj[(b*NP+tid)*2], s1 = obj[(b*NP+tid)*2+1];
    int m = (s1 > s0);
    g_mask[b*NP+tid] = m ? 1.f : 0.f;
    unsigned bal = __ballot_sync(~0u, m);
    int before = __popc(bal & ((1u<<lane)-1u));
    if (lane==0) wc[w] = __popc(bal);
    __syncthreads();
    if (tid < 32) {
        int v = wc[tid];
        #pragma unroll
        for (int o=1;o<32;o<<=1){ int t=__shfl_up_sync(~0u,v,o); if (lane>=o) v+=t; }
        wo[tid] = v - wc[tid];
        if (tid==31) { g_cntI[b] = v; g_cnt[b] = (float)v; }
    }
    __syncthreads();
    g_pos[b*NP+tid] = wo[w] + before;
    int cnt = g_cntI[b];
    int padded = (cnt + 127) & ~127;
    for (int e = cnt*NH + tid; e < padded*NH; e += 1024) {
        g_boxc [b*NP*NH + e] = 0u;
        g_boxlc[b*NP*NH + e] = 0u;
    }
}

// ---------------- targets (R14 version) ----------------
__global__ __launch_bounds__(1024) void k_tgt(const float* __restrict__ pc, const float* __restrict__ ps,
                      const float* __restrict__ gc, const float* __restrict__ gs) {
    int l = blockIdx.x, b = blockIdx.y, tid = threadIdx.x;
    int lane = tid & 31, w = tid >> 5;
    __shared__ float sg[6];
    __shared__ int red[32];
    float* trow = g_tgtc + (b*NL+l)*NP;
    trow[tid] = 0.f;
    if (tid < 3) { sg[tid] = gc[(b*NL+l)*3+tid]; sg[3+tid] = gs[(b*NL+l)*3+tid] + 0.01f; }
    __syncthreads();
    float volg = sg[3]*sg[4]*sg[5];
    int base = (b*NP+tid)*3;
    float inter = 1.f, volp = 1.f;
    #pragma unroll
    for (int d=0; d<3; d++) {
        float cc = pc[base+d], ss = ps[base+d];
        float lo = fmaxf(sg[d]-0.5f*sg[3+d], cc-ss*0.5f);
        float hi = fminf(sg[d]+0.5f*sg[3+d], cc+ss*0.5f);
        inter *= fmaxf(hi-lo, 0.f); volp *= ss;
    }
    float iou = inter / (volg + volp - inter + 1e-7f);
    bool pos_t = (iou > 0.25f) && (g_mask[b*NP+tid] > 0.f);
    if (pos_t) trow[g_pos[b*NP+tid]] = 1.f;
    unsigned bal = __ballot_sync(~0u, pos_t);
    if (lane == 0) red[w] = __popc(bal);
    __syncthreads();
    if (tid < 32) {
        int v = red[tid];
        #pragma unroll
        for (int o = 16; o; o >>= 1) v += __shfl_xor_sync(~0u, v, o);
        if (tid == 0) g_nl[b*NL+l] = (float)v;
    }
}

__device__ __forceinline__ unsigned f2tf(float f) {
    unsigned u; asm("cvt.rna.tf32.f32 %0, %1;" : "=r"(u) : "f"(f)); return u;
}
__device__ __forceinline__ uint4 f2tf4(float4 v) {
    return make_uint4(f2tf(v.x), f2tf(v.y), f2tf(v.z), f2tf(v.w));
}
__device__ __forceinline__ void mma_tf32(float* c, const unsigned* a, const unsigned* bb) {
    asm volatile("mma.sync.aligned.m16n8k8.row.col.f32.tf32.tf32.f32 "
                 "{%0,%1,%2,%3}, {%4,%5,%6,%7}, {%8,%9}, {%0,%1,%2,%3};"
                 : "+f"(c[0]), "+f"(c[1]), "+f"(c[2]), "+f"(c[3])
                 : "r"(a[0]), "r"(a[1]), "r"(a[2]), "r"(a[3]), "r"(bb[0]), "r"(bb[1]));
}
__device__ __forceinline__ int lang_num_at(const int* ln, int b) {
    return (ln[1] == 0) ? ln[2*b] : ln[b];
}

// ---------------- k_text: 32-row blocks, 512 thr, grid 32 ----------------
#define TEXT_SMEM ((128*SW + 32*SW)*4 + 8*32*4)
__global__ __launch_bounds__(512, 2) void k_text_tc(const float* __restrict__ emb,
                                                    const float* __restrict__ Wt) {
    extern __shared__ unsigned su[];
    unsigned* wt = su;                 // [128][SW]
    unsigned* av = su + 128*SW;        // [32][SW]
    float* pn = (float*)(su + 160*SW); // [8 colgrp][32 rows]
    const int r0 = blockIdx.x*32, tid = threadIdx.x;
    const float4* e4 = (const float4*)(emb + r0*NH);
    const float4* w4 = (const float4*)Wt;
    for (int idx = tid; idx < 4096; idx += 512) {
        int r = idx >> 5, k4 = idx & 31;
        *(uint4*)&wt[r*SW + k4*4] = f2tf4(w4[idx]);
    }
    for (int idx = tid; idx < 1024; idx += 512) {
        int r = idx >> 5, k4 = idx & 31;
        *(uint4*)&av[r*SW + k4*4] = f2tf4(e4[idx]);
    }
    __syncthreads();
    const int wid = tid>>5, lane = tid&31, g = lane>>2, t4 = lane&3;
    const int wm = wid & 1, wn = wid >> 1;   // 2 m-tiles x 8 col-groups(16 cols)
    float acc[2][4];
    #pragma unroll
    for (int nf=0;nf<2;nf++)
        #pragma unroll
        for (int i=0;i<4;i++) acc[nf][i]=0.f;
    #pragma unroll
    for (int ks = 0; ks < 16; ks++) {
        const int k0 = ks*8 + 2*t4;
        uint2 aP0 = *(uint2*)&av[(wm*16 + g)*SW + k0];
        uint2 aP1 = *(uint2*)&av[(wm*16 + g + 8)*SW + k0];
        unsigned af[4] = { aP0.x, aP1.x, aP0.y, aP1.y };
        #pragma unroll
        for (int nf = 0; nf < 2; nf++) {
            uint2 bP = *(uint2*)&wt[(wn*16 + nf*8 + g)*SW + k0];
            unsigned bf[2] = { bP.x, bP.y };
            mma_tf32(acc[nf], af, bf);
        }
    }
    float sA = 0.f, sB = 0.f;
    #pragma unroll
    for (int nf = 0; nf < 2; nf++) {
        sA += acc[nf][0]*acc[nf][0] + acc[nf][1]*acc[nf][1];
        sB += acc[nf][2]*acc[nf][2] + acc[nf][3]*acc[nf][3];
    }
    #pragma unroll
    for (int o = 1; o < 4; o <<= 1) {
        sA += __shfl_xor_sync(~0u, sA, o);
        sB += __shfl_xor_sync(~0u, sB, o);
    }
    const int rA = wm*16 + g, rB = rA + 8;
    if (t4 == 0) { pn[wn*32 + rA] = sA; pn[wn*32 + rB] = sB; }
    __syncthreads();
    float nA = 0.f, nB = 0.f;
    #pragma unroll
    for (int wg = 0; wg < 8; wg++) { nA += pn[wg*32 + rA]; nB += pn[wg*32 + rB]; }
    float iA = 1.f/fmaxf(sqrtf(nA), 1e-12f);
    float iB = 1.f/fmaxf(sqrtf(nB), 1e-12f);
    #pragma unroll
    for (int nf = 0; nf < 2; nf++) {
        int col = wn*16 + nf*8 + t4*2;
        *(float2*)&g_text[(r0+rA)*NH + col] = make_float2(acc[nf][0]*iA, acc[nf][1]*iA);
        *(float2*)&g_text[(r0+rB)*NH + col] = make_float2(acc[nf][2]*iB, acc[nf][3]*iB);
    }
}

// ---------------- k_proj: tf32 TC, paired-k LDS.64, 512 thr (R14) ----------------
#define PROJ_SMEM_B (3*128*SW*4)
__global__ __launch_bounds__(512) void k_proj(const float* __restrict__ bbox,
                                              const float* __restrict__ Wp,
                                              const float* __restrict__ Wpi) {
    extern __shared__ unsigned su[];
    unsigned* av = su;
    unsigned* wp = su + 128*SW;
    unsigned* wi = su + 2*128*SW;
    const int m0 = blockIdx.x*128, b = m0 >> 10;
    const int tid = threadIdx.x;
    const float4* a4 = (const float4*)(bbox + m0*NH);
    const float4* p4 = (const float4*)Wp;
    const float4* i4 = (const float4*)Wpi;
    for (int idx = tid; idx < 4096; idx += 512) {
        int r = idx >> 5, k4 = idx & 31;
        *(uint4*)&av[r*SW + k4*4] = f2tf4(a4[idx]);
        *(uint4*)&wp[r*SW + k4*4] = f2tf4(p4[idx]);
        *(uint4*)&wi[r*SW + k4*4] = f2tf4(i4[idx]);
    }
    __syncthreads();
    const int wid = tid>>5, lane = tid&31, g = lane>>2, t4 = lane&3;
    const int wm = wid & 7, wn = wid >> 3;
    const unsigned* wb = wn ? wi : wp;
    float acc[16][4];
    #pragma unroll
    for (int nf=0;nf<16;nf++)
        #pragma unroll
        for (int i=0;i<4;i++) acc[nf][i] = 0.f;
    #pragma unroll
    for (int ks = 0; ks < 16; ks++) {
        const int k0 = ks*8 + 2*t4;
        uint2 aP0 = *(uint2*)&av[(wm*16 + g)*SW + k0];
        uint2 aP1 = *(uint2*)&av[(wm*16 + g + 8)*SW + k0];
        unsigned af[4] = { aP0.x, aP1.x, aP0.y, aP1.y };
        #pragma unroll
        for (int nf = 0; nf < 16; nf++) {
            uint2 bP = *(uint2*)&wb[(nf*8 + g)*SW + k0];
            unsigned bf[2] = { bP.x, bP.y };
            mma_tf32(acc[nf], af, bf);
        }
    }
    float sA = 0.f, sB = 0.f;
    #pragma unroll
    for (int nf = 0; nf < 16; nf++) {
        sA += acc[nf][0]*acc[nf][0] + acc[nf][1]*acc[nf][1];
        sB += acc[nf][2]*acc[nf][2] + acc[nf][3]*acc[nf][3];
    }
    #pragma unroll
    for (int o = 1; o < 4; o <<= 1) {
        sA += __shfl_xor_sync(~0u, sA, o);
        sB += __shfl_xor_sync(~0u, sB, o);
    }
    float iA = 1.f/fmaxf(sqrtf(sA), 1e-12f);
    float iB = 1.f/fmaxf(sqrtf(sB), 1e-12f);
    const int rA = wm*16 + g, rB = rA + 8;
    unsigned* cbase = wn ? g_boxc : g_boxlc;
    #pragma unroll
    for (int rr = 0; rr < 2; rr++) {
        int gp = m0 + (rr ? rB : rA);
        float inv = rr ? iB : iA;
        if (g_mask[gp] > 0.f) {
            unsigned* cdst = cbase + ((long)b*NP + g_pos[gp])*NH + t4*2;
            #pragma unroll
            for (int nf = 0; nf < 16; nf++)
                *(uint2*)(cdst + nf*8) =
                    make_uint2(f2tf(acc[nf][rr*2]*inv), f2tf(acc[nf][rr*2+1]*inv));
        }
    }
}

// ---------------- k_iou: paired-k LDS.64 TC GEMM + masked row logsumexp (R14) ----------------
#define IOU_TC_SMEM (2*128*SW*4 + (128 + 2*2*128 + 2*128)*4)
__global__ __launch_bounds__(512) void k_iou_tc() {
    extern __shared__ unsigned smu[];
    unsigned* as = smu;
    unsigned* bs = smu + 128*SW;
    float* ms  = (float*)(smu + 2*128*SW);
    float* pm  = ms + 128;
    float* ps  = pm + 256;
    float* rmS = ps + 256;
    float* rsS = rmS + 128;

    const int b = blockIdx.y, r0 = blockIdx.x*128, tid = threadIdx.x;
    const int cnt = g_cntI[b];
    if (r0 >= cnt) return;
    const int qtiles = (cnt + 127) >> 7;
    const int wid = tid >> 5, lane = tid & 31;
    const int g = lane >> 2, t4 = lane & 3;
    const int wm = wid & 7, wn = wid >> 3;
    const uint4* Xa = (const uint4*)(g_boxc + ((long)b*NP + r0)*NH);

    for (int idx = tid; idx < 4096; idx += 512) {
        int r = idx >> 5, k4 = idx & 31;
        *(uint4*)&as[r*SW + k4*4] = Xa[idx];
    }
    if (tid < 128) { rmS[tid] = -1e30f; rsS[tid] = 0.f; }

    for (int qt = 0; qt < qtiles; qt++) {
        __syncthreads();
        const uint4* Xb = (const uint4*)(g_boxc + ((long)b*NP + qt*128)*NH);
        for (int idx = tid; idx < 4096; idx += 512) {
            int q = idx >> 5, k4 = idx & 31;
            *(uint4*)&bs[q*SW + k4*4] = Xb[idx];
        }
        if (tid < 128) ms[tid] = (qt*128 + tid < cnt) ? 1.f : 0.f;
        __syncthreads();

        float acc[8][4];
        #pragma unroll
        for (int nf=0;nf<8;nf++)
            #pragma unroll
            for (int i=0;i<4;i++) acc[nf][i] = 0.f;
        #pragma unroll
        for (int ks = 0; ks < 16; ks++) {
            const int k0 = ks*8 + 2*t4;
            uint2 aP0 = *(uint2*)&as[(wm*16 + g)*SW + k0];
            uint2 aP1 = *(uint2*)&as[(wm*16 + g + 8)*SW + k0];
            unsigned af[4] = { aP0.x, aP1.x, aP0.y, aP1.y };
            #pragma unroll
            for (int nf = 0; nf < 8; nf++) {
                uint2 bP = *(uint2*)&bs[(wn*64 + nf*8 + g)*SW + k0];
                unsigned bf[2] = { bP.x, bP.y };
                mma_tf32(acc[nf], af, bf);
            }
        }
        float cm0[8], cm1[8];
        #pragma unroll
        for (int nf = 0; nf < 8; nf++) {
            cm0[nf] = ms[wn*64 + nf*8 + t4*2];
            cm1[nf] = ms[wn*64 + nf*8 + t4*2 + 1];
        }
        {
            const int rA = wm*16 + g, rB = rA + 8;
            float mA = -1e30f, mB = -1e30f;
            #pragma unroll
            for (int nf = 0; nf < 8; nf++) {
                mA = fmaxf(mA, (cm0[nf] > 0.f) ? acc[nf][0] : -1e30f);
                mA = fmaxf(mA, (cm1[nf] > 0.f) ? acc[nf][1] : -1e30f);
                mB = fmaxf(mB, (cm0[nf] > 0.f) ? acc[nf][2] : -1e30f);
                mB = fmaxf(mB, (cm1[nf] > 0.f) ? acc[nf][3] : -1e30f);
            }
            #pragma unroll
            for (int o = 1; o < 4; o <<= 1) {
                mA = fmaxf(mA, __shfl_xor_sync(~0u, mA, o));
                mB = fmaxf(mB, __shfl_xor_sync(~0u, mB, o));
            }
            float eA = 0.f, eB = 0.f;
            #pragma unroll
            for (int nf = 0; nf < 8; nf++) {
                eA += (cm0[nf] > 0.f) ? __expf(acc[nf][0] - mA) : 0.f;
                eA += (cm1[nf] > 0.f) ? __expf(acc[nf][1] - mA) : 0.f;
                eB += (cm0[nf] > 0.f) ? __expf(acc[nf][2] - mB) : 0.f;
                eB += (cm1[nf] > 0.f) ? __expf(acc[nf][3] - mB) : 0.f;
            }
            #pragma unroll
            for (int o = 1; o < 4; o <<= 1) {
                eA += __shfl_xor_sync(~0u, eA, o);
                eB += __shfl_xor_sync(~0u, eB, o);
            }
            if (t4 == 0) {
                pm[wn*128 + rA] = mA; ps[wn*128 + rA] = eA;
                pm[wn*128 + rB] = mB; ps[wn*128 + rB] = eB;
            }
        }
        __syncthreads();
        if (tid < 128) {
            float m0 = pm[tid], s0 = ps[tid], m1 = pm[128+tid], s1 = ps[128+tid];
            float tm = fmaxf(m0, m1);
            float te = ((s0 > 0.f) ? s0*__expf(m0 - tm) : 0.f)
                     + ((s1 > 0.f) ? s1*__expf(m1 - tm) : 0.f);
            float rm = rmS[tid], nm = fmaxf(rm, tm);
            float rs = rsS[tid];
            rs = ((rs > 0.f) ? rs*__expf(rm - nm) : 0.f)
               + ((te > 0.f) ? te*__expf(tm - nm) : 0.f);
            rmS[tid] = nm; rsS[tid] = rs;
        }
    }
    __syncthreads();
    if (tid < 128) {
        int r = r0 + tid;
        if (r < cnt)
            g_lsec[b*NP + r] = (rsS[tid] > 0.f) ? rmS[tid] + logf(rsS[tid]) : 0.f;
    }
}

// ---------------- k_lang_part: paired-k LDS.64 (R14) ----------------
#define LANGP_SMEM ((32*SW + 128*SW)*4 + (128 + 3*256)*4)
__global__ __launch_bounds__(512) void k_lang_part() {
    const int qt = blockIdx.x, b = blockIdx.y, tid = threadIdx.x;
    const int cnt = g_cntI[b];
    if (qt*128 >= cnt) {
        if (tid < 32) {
            int o = (b*8+qt)*NL + tid;
            g_lpm[o] = -1e30f; g_lps[o] = 0.f; g_lpt[o] = 0.f;
        }
        return;
    }
    extern __shared__ unsigned smu[];
    unsigned* at = smu;
    unsigned* bs = smu + 32*SW;
    float* ms = (float*)(smu + 32*SW + 128*SW);
    float* pm = ms + 128;
    float* ps = pm + 256;
    float* pt = ps + 256;
    const int wid = tid >> 5, lane = tid & 31;
    const int g = lane >> 2, t4 = lane & 3;
    const int wm = wid & 1, wn = wid >> 1;

    const float4* tx4 = (const float4*)(g_text + b*NL*NH);
    for (int idx = tid; idx < 1024; idx += 512) {
        int r = idx >> 5, k4 = idx & 31;
        *(uint4*)&at[r*SW + k4*4] = f2tf4(tx4[idx]);
    }
    const uint4* Xb = (const uint4*)(g_boxlc + ((long)b*NP + qt*128)*NH);
    for (int idx = tid; idx < 4096; idx += 512) {
        int q = idx >> 5, k4 = idx & 31;
        *(uint4*)&bs[q*SW + k4*4] = Xb[idx];
    }
    if (tid < 128) ms[tid] = (qt*128 + tid < cnt) ? 1.f : 0.f;
    __syncthreads();

    float acc[2][4];
    #pragma unroll
    for (int nf=0;nf<2;nf++)
        #pragma unroll
        for (int i=0;i<4;i++) acc[nf][i] = 0.f;
    #pragma unroll
    for (int ks = 0; ks < 16; ks++) {
        const int k0 = ks*8 + 2*t4;
        uint2 aP0 = *(uint2*)&at[(wm*16 + g)*SW + k0];
        uint2 aP1 = *(uint2*)&at[(wm*16 + g + 8)*SW + k0];
        unsigned af[4] = { aP0.x, aP1.x, aP0.y, aP1.y };
        #pragma unroll
        for (int nf = 0; nf < 2; nf++) {
            uint2 bP = *(uint2*)&bs[(wn*16 + nf*8 + g)*SW + k0];
            unsigned bf[2] = { bP.x, bP.y };
            mma_tf32(acc[nf], af, bf);
        }
    }
    const int rA = wm*16 + g, rB = rA + 8;
    float mA = -1e30f, mB = -1e30f, tA = 0.f, tB = 0.f;
    float m0v[2], m1v[2];
    #pragma unroll
    for (int nf = 0; nf < 2; nf++) {
        int col0 = wn*16 + nf*8 + t4*2;
        m0v[nf] = ms[col0]; m1v[nf] = ms[col0 + 1];
        float2 tgA = *(float2*)&g_tgtc[(b*NL + rA)*NP + qt*128 + col0];
        float2 tgB = *(float2*)&g_tgtc[(b*NL + rB)*NP + qt*128 + col0];
        tA += tgA.x*acc[nf][0] + tgA.y*acc[nf][1];
        tB += tgB.x*acc[nf][2] + tgB.y*acc[nf][3];
        mA = fmaxf(mA, (m0v[nf] > 0.f) ? acc[nf][0] : -1e30f);
        mA = fmaxf(mA, (m1v[nf] > 0.f) ? acc[nf][1] : -1e30f);
        mB = fmaxf(mB, (m0v[nf] > 0.f) ? acc[nf][2] : -1e30f);
        mB = fmaxf(mB, (m1v[nf] > 0.f) ? acc[nf][3] : -1e30f);
    }
    #pragma unroll
    for (int o = 1; o < 4; o <<= 1) {
        mA = fmaxf(mA, __shfl_xor_sync(~0u, mA, o));
        mB = fmaxf(mB, __shfl_xor_sync(~0u, mB, o));
    }
    float eA = 0.f, eB = 0.f;
    #pragma unroll
    for (int nf = 0; nf < 2; nf++) {
        eA += (m0v[nf] > 0.f) ? __expf(acc[nf][0] - mA) : 0.f;
        eA += (m1v[nf] > 0.f) ? __expf(acc[nf][1] - mA) : 0.f;
        eB += (m0v[nf] > 0.f) ? __expf(acc[nf][2] - mB) : 0.f;
        eB += (m1v[nf] > 0.f) ? __expf(acc[nf][3] - mB) : 0.f;
    }
    #pragma unroll
    for (int o = 1; o < 4; o <<= 1) {
        eA += __shfl_xor_sync(~0u, eA, o);
        eB += __shfl_xor_sync(~0u, eB, o);
        tA += __shfl_xor_sync(~0u, tA, o);
        tB += __shfl_xor_sync(~0u, tB, o);
    }
    if (t4 == 0) {
        pm[wn*32 + rA] = mA; ps[wn*32 + rA] = eA; pt[wn*32 + rA] = tA;
        pm[wn*32 + rB] = mB; ps[wn*32 + rB] = eB; pt[wn*32 + rB] = tB;
    }
    __syncthreads();
    if (tid < 32) {
        float m = -1e30f, s = 0.f, t = 0.f;
        #pragma unroll
        for (int wg = 0; wg < 8; wg++) {
            float om = pm[wg*32 + tid], os = ps[wg*32 + tid];
            float nm = fmaxf(m, om);
            s = ((s > 0.f) ? s*__expf(m - nm) : 0.f)
              + ((os > 0.f) ? os*__expf(om - nm) : 0.f);
            m = nm;
            t += pt[wg*32 + tid];
        }
        int o = (b*8+qt)*NL + tid;
        g_lpm[o] = m; g_lps[o] = s; g_lpt[o] = t;
    }
}

// ---------------- k_vsum_part (tgtc bits pass-through) ----------------
#define VSP_SMEM ((32*132 + 128*132)*4)
__global__ __launch_bounds__(512) void k_vsum_part() {
    const int qt = blockIdx.x, b = blockIdx.y, tid = threadIdx.x;
    const int cnt = g_cntI[b];
    float4* vp = g_vp + (b*8+qt)*NL*32;
    if (qt*128 >= cnt) {
        for (int i = tid; i < NL*32; i += 512) vp[i] = make_float4(0.f,0.f,0.f,0.f);
        if (tid < 32) g_lsp[(b*8+qt)*NL + tid] = 0.f;
        return;
    }
    extern __shared__ unsigned smu[];
    unsigned* at = smu;
    unsigned* bs = smu + 32*132;
    const int wid = tid >> 5, lane = tid & 31;
    const int g = lane >> 2, t4 = lane & 3;
    const int wm = wid & 1, wn = wid >> 1;

    const uint4* tg4 = (const uint4*)(g_tgtc + b*NL*NP + qt*128);  // 0/1.0f are exact tf32
    for (int idx = tid; idx < 1024; idx += 512) {
        int r = idx >> 5, k4 = idx & 31;
        *(uint4*)&at[r*132 + k4*4] = tg4[r*256 + k4];
    }
    const uint4* Xb = (const uint4*)(g_boxc + ((long)b*NP + qt*128)*NH);
    for (int idx = tid; idx < 4096; idx += 512) {
        int q = idx >> 5, k4 = idx & 31;
        *(uint4*)&bs[q*132 + k4*4] = Xb[idx];
    }
    __syncthreads();

    float acc[2][4];
    #pragma unroll
    for (int nf=0;nf<2;nf++)
        #pragma unroll
        for (int i=0;i<4;i++) acc[nf][i] = 0.f;
    #pragma unroll
    for (int ks = 0; ks < 16; ks++) {
        const int k0 = ks*8;
        unsigned af[4];
        int base = (wm*16 + g)*132 + k0 + t4;
        af[0] = at[base];
        af[1] = at[base + 8*132];
        af[2] = at[base + 4];
        af[3] = at[base + 8*132 + 4];
        #pragma unroll
        for (int nf = 0; nf < 2; nf++) {
            int ncol = wn*16 + nf*8 + g;
            unsigned bf[2] = { bs[(k0+t4)*132 + ncol], bs[(k0+t4+4)*132 + ncol] };
            mma_tf32(acc[nf], af, bf);
        }
    }
    float* vpf = (float*)vp;
    const int rA = wm*16 + g, rB = rA + 8;
    #pragma unroll
    for (int nf = 0; nf < 2; nf++) {
        int col0 = wn*16 + nf*8 + t4*2;
        *(float2*)(vpf + rA*NH + col0) = make_float2(acc[nf][0], acc[nf][1]);
        *(float2*)(vpf + rB*NH + col0) = make_float2(acc[nf][2], acc[nf][3]);
    }
    int jmax = min(128, cnt - qt*128);
    #pragma unroll
    for (int li = 0; li < 2; li++) {
        int l = wid*2 + li;
        float s = 0.f;
        for (int j = lane; j < jmax; j += 32)
            s += g_tgtc[(b*NL+l)*NP + qt*128 + j] * g_lsec[b*NP + qt*128 + j];
        #pragma unroll
        for (int o = 16; o; o >>= 1) s += __shfl_xor_sync(~0u, s, o);
        if (lane == 0) g_lsp[(b*8+qt)*NL + l] = s;
    }
}

// ---------------- k_vfold ----------------
__global__ __launch_bounds__(1024) void k_vfold(const int* __restrict__ ln) {
    int b = blockIdx.x, tid = threadIdx.x;
    int l = tid >> 5, lane = tid & 31;
    float4 v = make_float4(0.f,0.f,0.f,0.f);
    #pragma unroll
    for (int qt = 0; qt < 8; qt++) {
        float4 p = g_vp[((b*8+qt)*NL + l)*32 + lane];
        v.x += p.x; v.y += p.y; v.z += p.z; v.w += p.w;
    }
    float vv = v.x*v.x + v.y*v.y + v.z*v.z + v.w*v.w;
    float s = (lane < 8) ? g_lsp[(b*8+lane)*NL + l] : 0.f;
    #pragma unroll
    for (int o = 16; o; o >>= 1) {
        vv += __shfl_xor_sync(~0u, vv, o);
        s  += __shfl_xor_sync(~0u, s, o);
    }
    if (lane == 0) {
        float n = g_nl[b*NL+l];
        float cnt1 = fmaxf(g_cnt[b], 1.f);
        float val = (n > 0.f) ? (n*s - vv)/(cnt1*cnt1) : 0.f;
        g_iou[b*NL+l] = (l < lang_num_at(ln, b)) ? val : 0.f;
    }
}

// ---------------- k_final ----------------
__global__ void k_final(const int* __restrict__ ln, float* __restrict__ out) {
    int tid = threadIdx.x;
    int b = tid >> 5, l = tid & 31;
    float m = -1e30f, s = 0.f, t = 0.f;
    #pragma unroll
    for (int qt = 0; qt < 8; qt++) {
        int o = (b*8+qt)*NL + l;
        float om = g_lpm[o], os = g_lps[o];
        float nm = fmaxf(m, om);
        s = ((s > 0.f) ? s*__expf(m - nm) : 0.f)
          + ((os > 0.f) ? os*__expf(om - nm) : 0.f);
        m = nm;
        t += g_lpt[o];
    }
    float n = g_nl[tid];
    float cnt1 = fmaxf(g_cnt[b], 1.f);
    float a = 0.f;
    if (n > 0.f && s > 0.f) a = 0.5f*(n*(m + logf(s)) - t)/cnt1;
    if (l >= lang_num_at(ln, b)) a = 0.f;
    float c = g_iou[tid];
    for (int o = 16; o; o >>= 1) {
        a += __shfl_xor_sync(~0u, a, o);
        c += __shfl_xor_sync(~0u, c, o);
    }
    __shared__ float ra[32], rc[32];
    if ((tid&31)==0) { ra[tid>>5]=a; rc[tid>>5]=c; }
    __syncthreads();
    if (tid < 32) {
        a = ra[tid]; c = rc[tid];
        for (int o = 16; o; o >>= 1) {
            a += __shfl_xor_sync(~0u, a, o);
            c += __shfl_xor_sync(~0u, c, o);
        }
        if (tid == 0) { out[0] = a/(float)NB; out[1] = c/(float)NB; }
    }
}

extern "C" void kernel_launch(void* const* d_in, const int* in_sizes, int n_in,
                              void* d_out, int out_size) {
    const float* pred_center = (const float*)d_in[0];
    const float* pred_size   = (const float*)d_in[1];
    const float* bbox        = (const float*)d_in[2];
    const float* gt_center   = (const float*)d_in[3];
    const float* gt_size     = (const float*)d_in[4];
    const float* lang_emb    = (const float*)d_in[5];
    const float* obj         = (const float*)d_in[6];
    const float* Wt          = (const float*)d_in[7];
    const float* Wp          = (const float*)d_in[8];
    const float* Wpi         = (const float*)d_in[9];
    const int*   lang_num    = (const int*)d_in[10];
    float* out = (float*)d_out;

    static bool attr_done = false;
    if (!attr_done) {
        cudaFuncSetAttribute(k_proj, cudaFuncAttributeMaxDynamicSharedMemorySize, PROJ_SMEM_B);
        cudaFuncSetAttribute(k_iou_tc, cudaFuncAttributeMaxDynamicSharedMemorySize, IOU_TC_SMEM);
        cudaFuncSetAttribute(k_text_tc, cudaFuncAttributeMaxDynamicSharedMemorySize, TEXT_SMEM);
        cudaFuncSetAttribute(k_lang_part, cudaFuncAttributeMaxDynamicSharedMemorySize, LANGP_SMEM);
        cudaFuncSetAttribute(k_vsum_part, cudaFuncAttributeMaxDynamicSharedMemorySize, VSP_SMEM);
        attr_done = true;
    }

    k_maskscan<<<NB, 1024>>>(obj);
    k_tgt<<<dim3(NL, NB), 1024>>>(pred_center, pred_size, gt_center, gt_size);
    k_text_tc<<<(NB*NL)/32, 512, TEXT_SMEM>>>(lang_emb, Wt);
    k_proj<<<(NB*NP)/128, 512, PROJ_SMEM_B>>>(bbox, Wp, Wpi);
    k_iou_tc<<<dim3(NP/128, NB), 512, IOU_TC_SMEM>>>();
    k_lang_part<<<dim3(8, NB), 512, LANGP_SMEM>>>();
    k_vsum_part<<<dim3(8, NB), 512, VSP_SMEM>>>();
    k_vfold<<<NB, 1024>>>(lang_num);
    k_final<<<1, 1024>>>(lang_num, out);
}